// round 17
// baseline (speedup 1.0000x reference)
#include <cuda_runtime.h>
#include <cstddef>

// GloVe loss — R12 aux pipeline (exact two-level counting sort by center)
// + main gather re-tuned for FULL occupancy: launch_bounds(256,8) forces
// <=32 regs (8 blocks/SM = 64 warps), bias loads lane-0-predicated.
// Launches: hist -> scan -> scatter -> sort2 -> main.

static constexpr int EMB           = 300;
static constexpr int NV4           = EMB / 4;       // 75 float4 per row
static constexpr int BATCH_N       = 262144;

static constexpr int BUCKET_SHIFT  = 7;
static constexpr int NB            = 1024;          // covers 100000>>7 = 782
static constexpr int NB_USED       = 782;
static constexpr int SORT_CAP      = 1024;

static constexpr int STHREADS      = 512;
static constexpr int SCHUNK        = 2048;
static constexpr int SBLOCKS      = BATCH_N / SCHUNK;   // 128
static constexpr int SPT           = SCHUNK / STHREADS;  // 4

static constexpr int THREADS       = 256;
static constexpr int WARPS_PER_BLK = THREADS / 32;  // 8
static constexpr int ROWS_PER_WARP = 8;
static constexpr int MBLOCKS       = BATCH_N / (WARPS_PER_BLK * ROWS_PER_WARP); // 4096

// Replay-safe: g_cnt zeroed by scan after read; g_base fully rewritten by
// scan; s_recs fully overwritten; g_acc/g_done reset by last main block.
__device__ int    g_cnt[NB];
__device__ int    g_base[NB];
__device__ int4   s_recs[BATCH_N];
__device__ double g_acc;
__device__ unsigned int g_done;

// ---- 1) histogram by c>>7 ---------------------------------------------------
__global__ __launch_bounds__(STHREADS) void glove_hist_kernel(
    const int* __restrict__ center)
{
    __shared__ int h[NB];
    const int tid  = threadIdx.x;
    const int idx0 = blockIdx.x * SCHUNK;
    for (int i = tid; i < NB; i += STHREADS) h[i] = 0;
    __syncthreads();
    #pragma unroll
    for (int k = 0; k < SPT; ++k) {
        const int c = __ldg(center + idx0 + k * STHREADS + tid);
        atomicAdd(&h[c >> BUCKET_SHIFT], 1);
    }
    __syncthreads();
    for (int b = tid; b < NB; b += STHREADS)
        if (h[b]) atomicAdd(&g_cnt[b], h[b]);
}

// ---- 2) exclusive scan; re-zero counts for replay ---------------------------
__global__ __launch_bounds__(NB) void glove_scan_kernel()
{
    __shared__ int tmp[NB];
    const int t = threadIdx.x;
    const int v = g_cnt[t];
    g_cnt[t] = 0;
    tmp[t] = v;
    __syncthreads();
    #pragma unroll
    for (int off = 1; off < NB; off <<= 1) {
        int u = (t >= off) ? tmp[t - off] : 0;
        __syncthreads();
        tmp[t] += u;
        __syncthreads();
    }
    g_base[t] = tmp[t] - v;
}

// ---- 3) bucketed scatter ----------------------------------------------------
// After this kernel, g_base[b] == END offset of bucket b.
__global__ __launch_bounds__(STHREADS) void glove_scatter_kernel(
    const int*   __restrict__ center,
    const int*   __restrict__ outside,
    const float* __restrict__ coocs,
    const float* __restrict__ weighting)
{
    __shared__ int h[NB];
    __shared__ int base[NB];
    const int tid  = threadIdx.x;
    const int idx0 = blockIdx.x * SCHUNK;

    for (int i = tid; i < NB; i += STHREADS) h[i] = 0;
    __syncthreads();

    int c[SPT];
    #pragma unroll
    for (int k = 0; k < SPT; ++k) {
        c[k] = __ldg(center + idx0 + k * STHREADS + tid);
        atomicAdd(&h[c[k] >> BUCKET_SHIFT], 1);
    }
    __syncthreads();
    for (int b = tid; b < NB; b += STHREADS) {
        const int n = h[b];
        base[b] = n ? atomicAdd(&g_base[b], n) : 0;
    }
    __syncthreads();
    for (int i = tid; i < NB; i += STHREADS) h[i] = 0;   // reuse as cursors
    __syncthreads();

    #pragma unroll
    for (int k = 0; k < SPT; ++k) {
        const int i = idx0 + k * STHREADS + tid;
        const int b = c[k] >> BUCKET_SHIFT;
        const int off = atomicAdd(&h[b], 1);
        int4 rec;
        rec.x = c[k];
        rec.y = __ldg(outside + i);
        rec.z = __float_as_int(__ldg(coocs + i));
        rec.w = __float_as_int(__ldg(weighting + i));
        s_recs[base[b] + off] = rec;
    }
}

// ---- 3b) in-bucket counting sort by c&127 (R12 version) ---------------------
__global__ __launch_bounds__(512) void glove_sort2_kernel()
{
    __shared__ int cnt[128];
    __shared__ int pos[128];
    __shared__ int wsum[4];
    const int b    = blockIdx.x;
    const int tid  = threadIdx.x;
    const int lane = tid & 31;
    const int warp = tid >> 5;
    const int s    = (b == 0) ? 0 : g_base[b - 1];
    const int n    = g_base[b] - s;
    if (n <= 0 || n > SORT_CAP) return;

    if (tid < 128) cnt[tid] = 0;
    __syncthreads();

    int4 r0, r1;
    const bool has0 = (tid < n);
    const bool has1 = (tid + 512 < n);
    if (has0) { r0 = __ldg(&s_recs[s + tid]);       atomicAdd(&cnt[r0.x & 127], 1); }
    if (has1) { r1 = __ldg(&s_recs[s + tid + 512]); atomicAdd(&cnt[r1.x & 127], 1); }
    __syncthreads();

    if (warp < 4) {
        const int idx = warp * 32 + lane;
        const int x   = cnt[idx];
        int incl = x;
        #pragma unroll
        for (int off = 1; off < 32; off <<= 1) {
            int u = __shfl_up_sync(0xffffffffu, incl, off);
            if (lane >= off) incl += u;
        }
        if (lane == 31) wsum[warp] = incl;
        __syncwarp();
        pos[idx] = incl - x;
    }
    __syncthreads();
    if (tid < 128) {
        const int w = tid >> 5;
        int add = 0;
        #pragma unroll
        for (int k = 0; k < 3; ++k) if (k < w) add += wsum[k];
        pos[tid] += add;
    }
    __syncthreads();

    if (has0) s_recs[s + atomicAdd(&pos[r0.x & 127], 1)] = r0;
    if (has1) s_recs[s + atomicAdd(&pos[r1.x & 127], 1)] = r1;
}

// ---- 4) main gather — full-occupancy tuning ---------------------------------
__global__ __launch_bounds__(THREADS, 8) void glove_main_kernel(
    const float* __restrict__ cemb,
    const float* __restrict__ oemb,
    const float* __restrict__ cbias,
    const float* __restrict__ obias,
    float*       __restrict__ out)
{
    const int lane  = threadIdx.x & 31;
    const int warp  = threadIdx.x >> 5;
    const int gwarp = blockIdx.x * WARPS_PER_BLK + warp;

    const float4* __restrict__ cemb4 = reinterpret_cast<const float4*>(cemb);
    const float4* __restrict__ oemb4 = reinterpret_cast<const float4*>(oemb);

    float wsum = 0.0f;
    int   prev = -1;
    float4 a0, a1, a2;
    float  cb = 0.0f;                    // meaningful on lane 0 only
    a0 = a1 = a2 = make_float4(0.f, 0.f, 0.f, 0.f);

    #pragma unroll 1
    for (int r = 0; r < ROWS_PER_WARP; ++r) {
        const int row = gwarp * ROWS_PER_WARP + r;
        const int4 rec = __ldg(&s_recs[row]);

        // Bias load: lane 0 only (sole consumer); issued early to hide latency.
        float obv = 0.0f;
        if (lane == 0) obv = __ldg(obias + rec.y);

        const unsigned oo = (unsigned)rec.y * (unsigned)NV4 + (unsigned)lane;
        float4 b0 = __ldg(oemb4 + oo);
        float4 b1 = __ldg(oemb4 + oo + 32);
        float4 b2 = make_float4(0.f, 0.f, 0.f, 0.f);
        if (lane < NV4 - 64) b2 = __ldg(oemb4 + oo + 64);

        if (rec.x != prev) {   // warp-uniform branch (records sorted by center)
            const unsigned co = (unsigned)rec.x * (unsigned)NV4 + (unsigned)lane;
            a0 = __ldg(cemb4 + co);
            a1 = __ldg(cemb4 + co + 32);
            a2 = make_float4(0.f, 0.f, 0.f, 0.f);
            if (lane < NV4 - 64) a2 = __ldg(cemb4 + co + 64);
            if (lane == 0) cb = __ldg(cbias + rec.x);
            prev = rec.x;
        }

        float dot = a0.x * b0.x + a0.y * b0.y + a0.z * b0.z + a0.w * b0.w;
        dot      += a1.x * b1.x + a1.y * b1.y + a1.z * b1.z + a1.w * b1.w;
        dot      += a2.x * b2.x + a2.y * b2.y + a2.z * b2.z + a2.w * b2.w;

        #pragma unroll
        for (int off = 16; off; off >>= 1)
            dot += __shfl_xor_sync(0xffffffffu, dot, off);

        if (lane == 0) {
            const float err = dot + cb + obv - __int_as_float(rec.z);
            wsum += __int_as_float(rec.w) * err * err;
        }
    }

    __shared__ float sh[WARPS_PER_BLK];
    if (lane == 0) sh[warp] = wsum;
    __syncthreads();

    if (threadIdx.x == 0) {
        float s = 0.0f;
        #pragma unroll
        for (int i = 0; i < WARPS_PER_BLK; ++i) s += sh[i];
        atomicAdd(&g_acc, (double)s);

        __threadfence();
        const unsigned t = atomicAdd(&g_done, 1u);
        if (t == (unsigned)(MBLOCKS - 1)) {
            const double v = atomicAdd(&g_acc, 0.0);
            out[0] = (float)v;
            g_acc  = 0.0;
            g_done = 0u;
        }
    }
}

extern "C" void kernel_launch(void* const* d_in, const int* in_sizes, int n_in,
                              void* d_out, int out_size) {
    const int*   center    = (const int*)  d_in[0];
    const int*   outside   = (const int*)  d_in[1];
    const float* coocs     = (const float*)d_in[2];
    const float* weighting = (const float*)d_in[3];
    const float* cemb      = (const float*)d_in[4];
    const float* oemb      = (const float*)d_in[5];
    const float* cbias     = (const float*)d_in[6];
    const float* obias     = (const float*)d_in[7];
    float* out = (float*)d_out;

    glove_hist_kernel<<<SBLOCKS, STHREADS>>>(center);
    glove_scan_kernel<<<1, NB>>>();
    glove_scatter_kernel<<<SBLOCKS, STHREADS>>>(center, outside, coocs, weighting);
    glove_sort2_kernel<<<NB_USED, 512>>>();
    glove_main_kernel<<<MBLOCKS, THREADS>>>(cemb, oemb, cbias, obias, out);
}